// round 15
// baseline (speedup 1.0000x reference)
#include <cuda_runtime.h>
#include <cuda_fp16.h>
#include <math.h>
#include <limits.h>

#define NN   50000
#define EE   800000
#define GG   512
#define HH   4
#define CC   64
#define HC   256      // H*C
#define DIN_ 128
#define DENC_ 256

#define MTILES 391          // (NN+127)/128
#define SCAT_BLOCKS 3125    // (EE+255)/256
#define PRE_BLOCKS 512
#define FC_GPB 4
#define FC_BLOCKS ((GG / FC_GPB) * 2)   // 256
#define KD (DENC_ + CC)     // 320
#define KHALF (KD / 2)      // 160

// ---------------- scratch (static device arrays; no allocation) ----------------
// INVARIANT (replay-safe): g_deg and g_done are zero at the start of every
// kernel_launch (zero-init initially; k_fc restores them at the end).
// g_pool/g_cnt are zeroed by k_pre at the START of each launch.
__device__ __half g_xl[NN * HC];     // 25.6 MB
__device__ __half g_xr[NN * HC];     // 25.6 MB
__device__ __half g_whl[DIN_ * HC];
__device__ __half g_whr[DIN_ * HC];
__device__ int   g_deg[NN];
__device__ int   g_off[NN + 1];
__device__ int   g_woff[NN];
__device__ int   g_csrc[EE];
__device__ float g_pool[GG * CC];
__device__ int   g_cnt[GG];
__device__ unsigned g_done;

// ---------------- mma helpers ----------------
__device__ __forceinline__ unsigned smem_u32(const void* p) {
    return (unsigned)__cvta_generic_to_shared(p);
}
__device__ __forceinline__ void ldm_x4(unsigned& r0, unsigned& r1, unsigned& r2,
                                       unsigned& r3, unsigned addr) {
    asm volatile("ldmatrix.sync.aligned.m8n8.x4.shared.b16 {%0,%1,%2,%3}, [%4];"
                 : "=r"(r0), "=r"(r1), "=r"(r2), "=r"(r3) : "r"(addr));
}
__device__ __forceinline__ void ldm_x4_t(unsigned& r0, unsigned& r1, unsigned& r2,
                                         unsigned& r3, unsigned addr) {
    asm volatile("ldmatrix.sync.aligned.m8n8.x4.trans.shared.b16 {%0,%1,%2,%3}, [%4];"
                 : "=r"(r0), "=r"(r1), "=r"(r2), "=r"(r3) : "r"(addr));
}
__device__ __forceinline__ void mma16816(float* d, const unsigned* a, const unsigned* b) {
    asm volatile(
        "mma.sync.aligned.m16n8k16.row.col.f32.f16.f16.f32 "
        "{%0,%1,%2,%3}, {%4,%5,%6,%7}, {%8,%9}, {%0,%1,%2,%3};"
        : "+f"(d[0]), "+f"(d[1]), "+f"(d[2]), "+f"(d[3])
        : "r"(a[0]), "r"(a[1]), "r"(a[2]), "r"(a[3]), "r"(b[0]), "r"(b[1]));
}

// ---------------- L1: weight convert + pool-zero + histogram + scan ------------
__global__ __launch_bounds__(1024) void k_pre(const float* __restrict__ Wl,
                                              const float* __restrict__ Wr,
                                              const int* __restrict__ ei) {
    const int i = blockIdx.x * 1024 + threadIdx.x;
    const int stride = gridDim.x * 1024;

    for (int j = i; j < DIN_ * HC / 2; j += stride) {
        float2 a = ((const float2*)Wl)[j];
        float2 b = ((const float2*)Wr)[j];
        ((__half2*)g_whl)[j] = __floats2half2_rn(a.x, a.y);
        ((__half2*)g_whr)[j] = __floats2half2_rn(b.x, b.y);
    }
    for (int j = i; j < GG * CC; j += stride) g_pool[j] = 0.f;
    for (int j = i; j < GG; j += stride) g_cnt[j] = 0;
    for (int t = i; t < EE; t += stride) atomicAdd(&g_deg[ei[EE + t]], 1);

    __threadfence();
    __syncthreads();
    __shared__ bool s_last;
    if (threadIdx.x == 0) {
        unsigned prev = atomicAdd(&g_done, 1u);
        s_last = (prev == (unsigned)(gridDim.x - 1));
    }
    __syncthreads();
    if (!s_last) return;
    __threadfence();

    __shared__ int warpsum[32];
    const int tid = threadIdx.x;
    const int per = (NN + 1023) / 1024;   // 49
    const int base = tid * per;
    int sum = 0;
    for (int k = 0; k < per; k++) {
        int idx = base + k;
        if (idx < NN) sum += g_deg[idx];
    }
    const int lane = tid & 31, wid = tid >> 5;
    int v = sum;
#pragma unroll
    for (int off = 1; off < 32; off <<= 1) {
        int u = __shfl_up_sync(0xffffffffu, v, off);
        if (lane >= off) v += u;
    }
    if (lane == 31) warpsum[wid] = v;
    __syncthreads();
    if (wid == 0) {
        int wv = warpsum[lane];
#pragma unroll
        for (int off = 1; off < 32; off <<= 1) {
            int u = __shfl_up_sync(0xffffffffu, wv, off);
            if (lane >= off) wv += u;
        }
        warpsum[lane] = wv;
    }
    __syncthreads();
    int excl = v - sum + (wid > 0 ? warpsum[wid - 1] : 0);
    int run = excl;
    for (int k = 0; k < per; k++) {
        int idx = base + k;
        if (idx < NN) {
            int c = g_deg[idx];
            g_off[idx] = run;
            g_woff[idx] = run;
            run += c;
        }
    }
    if (tid == 1023) g_off[NN] = run;
}

// ---------------- L2: fused CSR-scatter + GEMM (A once, B double-buffered) ------
__global__ __launch_bounds__(256) void k_mid(const float* __restrict__ x,
                                             const float* __restrict__ bl,
                                             const float* __restrict__ br,
                                             const int* __restrict__ ei) {
    __shared__ __half sA[128 * 128];     // 32 KB
    __shared__ __half sB[2][128 * 64];   // 32 KB

    const int tid = threadIdx.x;
    int fb = blockIdx.x;

    if (fb < SCAT_BLOCKS) {           // ---- scatter part ----
        int t = fb * 256 + tid;
        if (t < EE) {
            int dst = ei[EE + t];
            int pos = atomicAdd(&g_woff[dst], 1);
            g_csrc[pos] = ei[t];
        }
        return;
    }
    const int mb = fb - SCAT_BLOCKS;  // ---- gemm part ----
    const int bm = mb * 128;

    // A tile once: fp32 -> half, swizzled
#pragma unroll
    for (int it = 0; it < 16; it++) {
        int q = it * 256 + tid;
        int row = q >> 5, c4 = q & 31;
        int gm = bm + row;
        float4 v = make_float4(0.f, 0.f, 0.f, 0.f);
        if (gm < NN) v = *(const float4*)&x[gm * DIN_ + c4 * 4];
        __half2 h0 = __floats2half2_rn(v.x, v.y);
        __half2 h1 = __floats2half2_rn(v.z, v.w);
        int cc = c4 >> 1, sub = (c4 & 1) << 2;
        uint2 pk;
        pk.x = *(unsigned*)&h0; pk.y = *(unsigned*)&h1;
        *(uint2*)&sA[row * 128 + ((cc ^ (row & 7)) << 3) + sub] = pk;
    }
    // preload B of stage 0 (whl, bn=0)
#pragma unroll
    for (int it = 0; it < 4; it++) {
        int q = it * 256 + tid;
        int r2_ = q >> 3, cc = q & 7;
        uint4 v = *(const uint4*)&g_whl[r2_ * HC + 0 + cc * 8];
        *(uint4*)&sB[0][r2_ * 64 + ((cc ^ (r2_ & 7)) << 3)] = v;
    }
    __syncthreads();

    const int wid = tid >> 5, lane = tid & 31;
    const int wm = (wid & 3) * 32;
    const int wn = (wid >> 2) * 32;

#pragma unroll 1
    for (int stage = 0; stage < 8; stage++) {
        const int cur = stage & 1;
        const int z = stage >> 2;
        const int nb = stage & 3;
        const float* bias = z ? br : bl;
        __half* out       = z ? g_xr : g_xl;
        const int bn = nb * 64;

        // prefetch next stage's B into registers (overlaps with MMAs)
        uint4 vnext[4];
        int nrow[4], ncc[4];
        if (stage < 7) {
            const int ns = stage + 1;
            const __half* Wn = (ns >> 2) ? g_whr : g_whl;
            const int nbn = (ns & 3) * 64;
#pragma unroll
            for (int it = 0; it < 4; it++) {
                int q = it * 256 + tid;
                nrow[it] = q >> 3; ncc[it] = q & 7;
                vnext[it] = *(const uint4*)&Wn[nrow[it] * HC + nbn + ncc[it] * 8];
            }
        }

        float acc[2][4][4];
#pragma unroll
        for (int i = 0; i < 2; i++)
#pragma unroll
            for (int j = 0; j < 4; j++)
#pragma unroll
                for (int k = 0; k < 4; k++) acc[i][j][k] = 0.f;

#pragma unroll
        for (int ks = 0; ks < 8; ks++) {
            const int k0 = ks * 16;
            unsigned a[2][4], b[4][2];
#pragma unroll
            for (int am = 0; am < 2; am++) {
                int row = wm + am * 16 + (lane & 15);
                int cc = (k0 >> 3) + (lane >> 4);
                unsigned addr = smem_u32(&sA[row * 128 + ((cc ^ (row & 7)) << 3)]);
                ldm_x4(a[am][0], a[am][1], a[am][2], a[am][3], addr);
            }
#pragma unroll
            for (int bt = 0; bt < 2; bt++) {
                int row = k0 + (lane & 15);
                int cc = ((wn + bt * 16) >> 3) + (lane >> 4);
                unsigned addr = smem_u32(&sB[cur][row * 64 + ((cc ^ (row & 7)) << 3)]);
                unsigned r0, r1, r2, r3;
                ldm_x4_t(r0, r1, r2, r3, addr);
                b[bt * 2 + 0][0] = r0; b[bt * 2 + 0][1] = r1;
                b[bt * 2 + 1][0] = r2; b[bt * 2 + 1][1] = r3;
            }
#pragma unroll
            for (int am = 0; am < 2; am++)
#pragma unroll
                for (int bt = 0; bt < 4; bt++) mma16816(acc[am][bt], a[am], b[bt]);
        }

        // epilogue store
#pragma unroll
        for (int am = 0; am < 2; am++) {
            int row0 = bm + wm + am * 16 + (lane >> 2);
#pragma unroll
            for (int bt = 0; bt < 4; bt++) {
                int col = bn + wn + bt * 8 + (lane & 3) * 2;
                float b0 = bias[col], b1 = bias[col + 1];
                if (row0 < NN)
                    *(__half2*)&out[row0 * HC + col] =
                        __floats2half2_rn(acc[am][bt][0] + b0, acc[am][bt][1] + b1);
                if (row0 + 8 < NN)
                    *(__half2*)&out[(row0 + 8) * HC + col] =
                        __floats2half2_rn(acc[am][bt][2] + b0, acc[am][bt][3] + b1);
            }
        }

        if (stage < 7) {
#pragma unroll
            for (int it = 0; it < 4; it++)
                *(uint4*)&sB[1 - cur][nrow[it] * 64 + ((ncc[it] ^ (nrow[it] & 7)) << 3)] = vnext[it];
        }
        __syncthreads();
    }
}

// ---------------- L3: fused attention + aggregate + pool (4-edge batches) ------
__global__ __launch_bounds__(256, 5) void k_node(const float* __restrict__ att,
                                                 const float* __restrict__ bgnn,
                                                 const int* __restrict__ batch) {
    const int lane = threadIdx.x & 31;
    int w = (blockIdx.x * blockDim.x + threadIdx.x) >> 5;
    const int nw = (gridDim.x * blockDim.x) >> 5;

    __half2 at2[4];
    {
        const float4 a0 = *(const float4*)&att[lane * 8 + 0];
        const float4 a1 = *(const float4*)&att[lane * 8 + 4];
        at2[0] = __floats2half2_rn(a0.x, a0.y);
        at2[1] = __floats2half2_rn(a0.z, a0.w);
        at2[2] = __floats2half2_rn(a1.x, a1.y);
        at2[3] = __floats2half2_rn(a1.z, a1.w);
    }
    const __half2 C02 = __float2half2_rn(0.2f);

    for (int n = w; n < NN; n += nw) {
        __half2 r2[4];
        {
            uint4 ur = *(const uint4*)&g_xr[n * HC + lane * 8];
            const __half2* rh = (const __half2*)&ur;
            r2[0] = rh[0]; r2[1] = rh[1]; r2[2] = rh[2]; r2[3] = rh[3];
        }

        __half2 acc2[4];
        acc2[0] = __float2half2_rn(0.f);
        acc2[1] = acc2[0]; acc2[2] = acc2[0]; acc2[3] = acc2[0];
        float D = 0.f;

        auto doedge1 = [&](uint4 ul) {
            const __half2* lh = (const __half2*)&ul;
            __half2 ps = __float2half2_rn(0.f);
#pragma unroll
            for (int i = 0; i < 4; i++) {
                __half2 z = __hadd2(lh[i], r2[i]);
                __half2 lk = __hmax2(z, __hmul2(z, C02));
                ps = __hfma2(lk, at2[i], ps);
            }
            float2 pf = __half22float2(ps);
            float p = pf.x + pf.y;
            p += __shfl_xor_sync(0xffffffffu, p, 4);
            p += __shfl_xor_sync(0xffffffffu, p, 2);
            p += __shfl_xor_sync(0xffffffffu, p, 1);
            const float a = __expf(p - 6.0f);
            D += a;
            const __half2 a2 = __float2half2_rn(a);
#pragma unroll
            for (int i = 0; i < 4; i++) acc2[i] = __hfma2(a2, lh[i], acc2[i]);
        };

        auto doedge2 = [&](uint4 ul0, uint4 ul1) {
            const __half2* lh0 = (const __half2*)&ul0;
            const __half2* lh1 = (const __half2*)&ul1;
            __half2 ps0 = __float2half2_rn(0.f);
            __half2 ps1 = ps0;
#pragma unroll
            for (int i = 0; i < 4; i++) {
                __half2 z0 = __hadd2(lh0[i], r2[i]);
                __half2 z1 = __hadd2(lh1[i], r2[i]);
                ps0 = __hfma2(__hmax2(z0, __hmul2(z0, C02)), at2[i], ps0);
                ps1 = __hfma2(__hmax2(z1, __hmul2(z1, C02)), at2[i], ps1);
            }
            __half2 ph = __hadd2(__lows2half2(ps0, ps1), __highs2half2(ps0, ps1));
#pragma unroll
            for (int s = 4; s > 0; s >>= 1) {
                unsigned pu = __shfl_xor_sync(0xffffffffu, *(unsigned*)&ph, s);
                ph = __hadd2(ph, *(__half2*)&pu);
            }
            float2 pf = __half22float2(ph);
            float a0 = __expf(pf.x - 6.0f);
            float a1 = __expf(pf.y - 6.0f);
            D += a0 + a1;
            const __half2 ah0 = __float2half2_rn(a0);
            const __half2 ah1 = __float2half2_rn(a1);
#pragma unroll
            for (int i = 0; i < 4; i++) {
                acc2[i] = __hfma2(ah0, lh0[i], acc2[i]);
                acc2[i] = __hfma2(ah1, lh1[i], acc2[i]);
            }
        };

        doedge1(*(const uint4*)&g_xl[n * HC + lane * 8]);   // self loop

        const int beg = g_off[n], end = g_off[n + 1];
        int e = beg;
        // 4 edges in flight: 4 index loads, then 4 independent gathers
        for (; e + 3 < end; e += 4) {
            const int s0 = g_csrc[e],     s1 = g_csrc[e + 1];
            const int s2 = g_csrc[e + 2], s3 = g_csrc[e + 3];
            uint4 u0 = *(const uint4*)&g_xl[s0 * HC + lane * 8];
            uint4 u1 = *(const uint4*)&g_xl[s1 * HC + lane * 8];
            uint4 u2 = *(const uint4*)&g_xl[s2 * HC + lane * 8];
            uint4 u3 = *(const uint4*)&g_xl[s3 * HC + lane * 8];
            doedge2(u0, u1);
            doedge2(u2, u3);
        }
        if (e + 1 < end) {
            const int s0 = g_csrc[e], s1 = g_csrc[e + 1];
            uint4 u0 = *(const uint4*)&g_xl[s0 * HC + lane * 8];
            uint4 u1 = *(const uint4*)&g_xl[s1 * HC + lane * 8];
            doedge2(u0, u1);
            e += 2;
        }
        if (e < end) {
            const int s = g_csrc[e];
            doedge1(*(const uint4*)&g_xl[s * HC + lane * 8]);
        }

        const float inv = 1.f / (D + 1e-16f);
        float v[8];
#pragma unroll
        for (int i = 0; i < 4; i++) {
            float2 af = __half22float2(acc2[i]);
            float t0 = af.x * inv, t1 = af.y * inv;
            t0 += __shfl_xor_sync(0xffffffffu, t0, 8);
            t0 += __shfl_xor_sync(0xffffffffu, t0, 16);
            t1 += __shfl_xor_sync(0xffffffffu, t1, 8);
            t1 += __shfl_xor_sync(0xffffffffu, t1, 16);
            v[2 * i] = t0; v[2 * i + 1] = t1;
        }

        if (lane < 8) {
            const int g = batch[n];
            if (lane == 0) atomicAdd(&g_cnt[g], 1);
#pragma unroll
            for (int j = 0; j < 8; j++) {
                const int c = lane * 8 + j;
                float val = fmaf(0.25f, v[j], bgnn[c]);
                val = fmaxf(val, 0.01f * val);
                atomicAdd(&g_pool[g * CC + c], val);
            }
        }
    }
}

// ---------------- L4: final FC (4 graphs x 128 cols x 2 k-halves) ---------------
__global__ __launch_bounds__(256) void k_fc(const float* __restrict__ hy,
                                            const float* __restrict__ Wfc,
                                            const float* __restrict__ bfc,
                                            float* __restrict__ out) {
    const int gb = (blockIdx.x >> 1) * FC_GPB;
    const int ch = blockIdx.x & 1;
    const int j = threadIdx.x;
    const int cj = j & 127;
    const int col = ch * 128 + cj;
    const int kh = j >> 7;
    __shared__ float sh[FC_GPB][KD];
    __shared__ float red[FC_GPB][128];

#pragma unroll
    for (int gi = 0; gi < FC_GPB; gi++) {
        const int g = gb + gi;
        sh[gi][j] = hy[g * DENC_ + j];
        if (j < CC) {
            int c = g_cnt[g];
            float cn = c > 0 ? (float)c : 1.f;
            sh[gi][DENC_ + j] = g_pool[g * CC + j] / cn;
        }
    }
    __syncthreads();

    for (int t = blockIdx.x * 256 + j; t < NN; t += FC_BLOCKS * 256) g_deg[t] = 0;
    if (blockIdx.x == 0 && j == 0) g_done = 0u;

    float acc[FC_GPB];
#pragma unroll
    for (int gi = 0; gi < FC_GPB; gi++) acc[gi] = (kh == 0) ? bfc[col] : 0.f;

    const int k0 = kh * KHALF;
#pragma unroll 8
    for (int k = k0; k < k0 + KHALF; k++) {
        const float wv = Wfc[k * DENC_ + col];
#pragma unroll
        for (int gi = 0; gi < FC_GPB; gi++) acc[gi] = fmaf(sh[gi][k], wv, acc[gi]);
    }

    if (kh == 1) {
#pragma unroll
        for (int gi = 0; gi < FC_GPB; gi++) red[gi][cj] = acc[gi];
    }
    __syncthreads();
    if (kh == 0) {
#pragma unroll
        for (int gi = 0; gi < FC_GPB; gi++)
            out[(gb + gi) * DENC_ + col] = acc[gi] + red[gi][cj];
    }
}

// ---------------- launch ----------------
extern "C" void kernel_launch(void* const* d_in, const int* in_sizes, int n_in,
                              void* d_out, int out_size) {
    const float* hy   = (const float*)d_in[0];
    const float* x    = (const float*)d_in[1];
    const int*   ei   = (const int*)d_in[2];
    const int*   batch= (const int*)d_in[3];
    const float* Wl   = (const float*)d_in[4];
    const float* bl   = (const float*)d_in[5];
    const float* Wr   = (const float*)d_in[6];
    const float* br   = (const float*)d_in[7];
    const float* att  = (const float*)d_in[8];
    const float* bgnn = (const float*)d_in[9];
    const float* Wfc  = (const float*)d_in[10];
    const float* bfc  = (const float*)d_in[11];
    float* out = (float*)d_out;

    k_pre<<<PRE_BLOCKS, 1024>>>(Wl, Wr, ei);                   // #1
    k_mid<<<SCAT_BLOCKS + MTILES, 256>>>(x, bl, br, ei);       // #2
    k_node<<<(NN + 7) / 8, 256>>>(att, bgnn, batch);           // #3
    k_fc<<<FC_BLOCKS, 256>>>(hy, Wfc, bfc, out);               // #4 (profiled)
}

// round 16
// speedup vs baseline: 1.0598x; 1.0598x over previous
#include <cuda_runtime.h>
#include <cuda_fp16.h>
#include <math.h>
#include <limits.h>

#define NN   50000
#define EE   800000
#define GG   512
#define HH   4
#define CC   64
#define HC   256      // H*C
#define DIN_ 128
#define DENC_ 256

#define MTILES 391          // (NN+127)/128
#define SCAT_BLOCKS 3125    // (EE+255)/256
#define PRE_BLOCKS 512
#define FC_GPB 4
#define FC_BLOCKS ((GG / FC_GPB) * 2)   // 256
#define KD (DENC_ + CC)     // 320
#define KHALF (KD / 2)      // 160

// ---------------- scratch (static device arrays; no allocation) ----------------
// INVARIANT (replay-safe): g_deg and g_done are zero at the start of every
// kernel_launch (zero-init initially; k_fc restores them at the end).
// g_pool/g_cnt are zeroed by k_pre at the START of each launch.
__device__ __half g_xl[NN * HC];     // 25.6 MB
__device__ __half g_xr[NN * HC];     // 25.6 MB
__device__ __half g_whl[DIN_ * HC];
__device__ __half g_whr[DIN_ * HC];
__device__ int   g_deg[NN];
__device__ int   g_off[NN + 1];
__device__ int   g_woff[NN];
__device__ int   g_csrc[EE];
__device__ float g_pool[GG * CC];
__device__ int   g_cnt[GG];
__device__ unsigned g_done;

// ---------------- mma helpers ----------------
__device__ __forceinline__ unsigned smem_u32(const void* p) {
    return (unsigned)__cvta_generic_to_shared(p);
}
__device__ __forceinline__ void ldm_x4(unsigned& r0, unsigned& r1, unsigned& r2,
                                       unsigned& r3, unsigned addr) {
    asm volatile("ldmatrix.sync.aligned.m8n8.x4.shared.b16 {%0,%1,%2,%3}, [%4];"
                 : "=r"(r0), "=r"(r1), "=r"(r2), "=r"(r3) : "r"(addr));
}
__device__ __forceinline__ void ldm_x4_t(unsigned& r0, unsigned& r1, unsigned& r2,
                                         unsigned& r3, unsigned addr) {
    asm volatile("ldmatrix.sync.aligned.m8n8.x4.trans.shared.b16 {%0,%1,%2,%3}, [%4];"
                 : "=r"(r0), "=r"(r1), "=r"(r2), "=r"(r3) : "r"(addr));
}
__device__ __forceinline__ void mma16816(float* d, const unsigned* a, const unsigned* b) {
    asm volatile(
        "mma.sync.aligned.m16n8k16.row.col.f32.f16.f16.f32 "
        "{%0,%1,%2,%3}, {%4,%5,%6,%7}, {%8,%9}, {%0,%1,%2,%3};"
        : "+f"(d[0]), "+f"(d[1]), "+f"(d[2]), "+f"(d[3])
        : "r"(a[0]), "r"(a[1]), "r"(a[2]), "r"(a[3]), "r"(b[0]), "r"(b[1]));
}

// ---------------- L1: weight convert + pool-zero + histogram + scan ------------
__global__ __launch_bounds__(1024) void k_pre(const float* __restrict__ Wl,
                                              const float* __restrict__ Wr,
                                              const int* __restrict__ ei) {
    const int i = blockIdx.x * 1024 + threadIdx.x;
    const int stride = gridDim.x * 1024;

    for (int j = i; j < DIN_ * HC / 2; j += stride) {
        float2 a = ((const float2*)Wl)[j];
        float2 b = ((const float2*)Wr)[j];
        ((__half2*)g_whl)[j] = __floats2half2_rn(a.x, a.y);
        ((__half2*)g_whr)[j] = __floats2half2_rn(b.x, b.y);
    }
    for (int j = i; j < GG * CC; j += stride) g_pool[j] = 0.f;
    for (int j = i; j < GG; j += stride) g_cnt[j] = 0;
    for (int t = i; t < EE; t += stride) atomicAdd(&g_deg[ei[EE + t]], 1);

    __threadfence();
    __syncthreads();
    __shared__ bool s_last;
    if (threadIdx.x == 0) {
        unsigned prev = atomicAdd(&g_done, 1u);
        s_last = (prev == (unsigned)(gridDim.x - 1));
    }
    __syncthreads();
    if (!s_last) return;
    __threadfence();

    __shared__ int warpsum[32];
    const int tid = threadIdx.x;
    const int per = (NN + 1023) / 1024;   // 49
    const int base = tid * per;
    int sum = 0;
    for (int k = 0; k < per; k++) {
        int idx = base + k;
        if (idx < NN) sum += g_deg[idx];
    }
    const int lane = tid & 31, wid = tid >> 5;
    int v = sum;
#pragma unroll
    for (int off = 1; off < 32; off <<= 1) {
        int u = __shfl_up_sync(0xffffffffu, v, off);
        if (lane >= off) v += u;
    }
    if (lane == 31) warpsum[wid] = v;
    __syncthreads();
    if (wid == 0) {
        int wv = warpsum[lane];
#pragma unroll
        for (int off = 1; off < 32; off <<= 1) {
            int u = __shfl_up_sync(0xffffffffu, wv, off);
            if (lane >= off) wv += u;
        }
        warpsum[lane] = wv;
    }
    __syncthreads();
    int excl = v - sum + (wid > 0 ? warpsum[wid - 1] : 0);
    int run = excl;
    for (int k = 0; k < per; k++) {
        int idx = base + k;
        if (idx < NN) {
            int c = g_deg[idx];
            g_off[idx] = run;
            g_woff[idx] = run;
            run += c;
        }
    }
    if (tid == 1023) g_off[NN] = run;
}

// ---------------- L2: fused GEMM + CSR-scatter (GEMM blocks FIRST) --------------
// blocks [0, MTILES): 128-row m-tile GEMM (the long pole -> wave 1).
// blocks [MTILES, MTILES+SCAT_BLOCKS): CSR scatter (overlaps with GEMM).
__global__ __launch_bounds__(256) void k_mid(const float* __restrict__ x,
                                             const float* __restrict__ bl,
                                             const float* __restrict__ br,
                                             const int* __restrict__ ei) {
    __shared__ __half sA[128 * 128];     // 32 KB
    __shared__ __half sB[2][128 * 64];   // 32 KB

    const int tid = threadIdx.x;
    const int fb = blockIdx.x;

    if (fb >= MTILES) {               // ---- scatter part ----
        int t = (fb - MTILES) * 256 + tid;
        if (t < EE) {
            int dst = ei[EE + t];
            int pos = atomicAdd(&g_woff[dst], 1);
            g_csrc[pos] = ei[t];
        }
        return;
    }
    const int bm = fb * 128;          // ---- gemm part ----

    // A tile once: fp32 -> half, swizzled
#pragma unroll
    for (int it = 0; it < 16; it++) {
        int q = it * 256 + tid;
        int row = q >> 5, c4 = q & 31;
        int gm = bm + row;
        float4 v = make_float4(0.f, 0.f, 0.f, 0.f);
        if (gm < NN) v = *(const float4*)&x[gm * DIN_ + c4 * 4];
        __half2 h0 = __floats2half2_rn(v.x, v.y);
        __half2 h1 = __floats2half2_rn(v.z, v.w);
        int cc = c4 >> 1, sub = (c4 & 1) << 2;
        uint2 pk;
        pk.x = *(unsigned*)&h0; pk.y = *(unsigned*)&h1;
        *(uint2*)&sA[row * 128 + ((cc ^ (row & 7)) << 3) + sub] = pk;
    }
    // preload B of stage 0 (whl, bn=0)
#pragma unroll
    for (int it = 0; it < 4; it++) {
        int q = it * 256 + tid;
        int r2_ = q >> 3, cc = q & 7;
        uint4 v = *(const uint4*)&g_whl[r2_ * HC + 0 + cc * 8];
        *(uint4*)&sB[0][r2_ * 64 + ((cc ^ (r2_ & 7)) << 3)] = v;
    }
    __syncthreads();

    const int wid = tid >> 5, lane = tid & 31;
    const int wm = (wid & 3) * 32;
    const int wn = (wid >> 2) * 32;

#pragma unroll 1
    for (int stage = 0; stage < 8; stage++) {
        const int cur = stage & 1;
        const int z = stage >> 2;
        const int nb = stage & 3;
        const float* bias = z ? br : bl;
        __half* out       = z ? g_xr : g_xl;
        const int bn = nb * 64;

        // prefetch next stage's B into registers (overlaps with MMAs)
        uint4 vnext[4];
        int nrow[4], ncc[4];
        if (stage < 7) {
            const int ns = stage + 1;
            const __half* Wn = (ns >> 2) ? g_whr : g_whl;
            const int nbn = (ns & 3) * 64;
#pragma unroll
            for (int it = 0; it < 4; it++) {
                int q = it * 256 + tid;
                nrow[it] = q >> 3; ncc[it] = q & 7;
                vnext[it] = *(const uint4*)&Wn[nrow[it] * HC + nbn + ncc[it] * 8];
            }
        }

        float acc[2][4][4];
#pragma unroll
        for (int i = 0; i < 2; i++)
#pragma unroll
            for (int j = 0; j < 4; j++)
#pragma unroll
                for (int k = 0; k < 4; k++) acc[i][j][k] = 0.f;

#pragma unroll
        for (int ks = 0; ks < 8; ks++) {
            const int k0 = ks * 16;
            unsigned a[2][4], b[4][2];
#pragma unroll
            for (int am = 0; am < 2; am++) {
                int row = wm + am * 16 + (lane & 15);
                int cc = (k0 >> 3) + (lane >> 4);
                unsigned addr = smem_u32(&sA[row * 128 + ((cc ^ (row & 7)) << 3)]);
                ldm_x4(a[am][0], a[am][1], a[am][2], a[am][3], addr);
            }
#pragma unroll
            for (int bt = 0; bt < 2; bt++) {
                int row = k0 + (lane & 15);
                int cc = ((wn + bt * 16) >> 3) + (lane >> 4);
                unsigned addr = smem_u32(&sB[cur][row * 64 + ((cc ^ (row & 7)) << 3)]);
                unsigned r0, r1, r2, r3;
                ldm_x4_t(r0, r1, r2, r3, addr);
                b[bt * 2 + 0][0] = r0; b[bt * 2 + 0][1] = r1;
                b[bt * 2 + 1][0] = r2; b[bt * 2 + 1][1] = r3;
            }
#pragma unroll
            for (int am = 0; am < 2; am++)
#pragma unroll
                for (int bt = 0; bt < 4; bt++) mma16816(acc[am][bt], a[am], b[bt]);
        }

        // epilogue store
#pragma unroll
        for (int am = 0; am < 2; am++) {
            int row0 = bm + wm + am * 16 + (lane >> 2);
#pragma unroll
            for (int bt = 0; bt < 4; bt++) {
                int col = bn + wn + bt * 8 + (lane & 3) * 2;
                float b0 = bias[col], b1 = bias[col + 1];
                if (row0 < NN)
                    *(__half2*)&out[row0 * HC + col] =
                        __floats2half2_rn(acc[am][bt][0] + b0, acc[am][bt][1] + b1);
                if (row0 + 8 < NN)
                    *(__half2*)&out[(row0 + 8) * HC + col] =
                        __floats2half2_rn(acc[am][bt][2] + b0, acc[am][bt][3] + b1);
            }
        }

        if (stage < 7) {
#pragma unroll
            for (int it = 0; it < 4; it++)
                *(uint4*)&sB[1 - cur][nrow[it] * 64 + ((ncc[it] ^ (nrow[it] & 7)) << 3)] = vnext[it];
        }
        __syncthreads();
    }
}

// ---------------- L3: fused attention + aggregate + pool (paired edges) --------
__global__ __launch_bounds__(256, 6) void k_node(const float* __restrict__ att,
                                                 const float* __restrict__ bgnn,
                                                 const int* __restrict__ batch) {
    const int lane = threadIdx.x & 31;
    int w = (blockIdx.x * blockDim.x + threadIdx.x) >> 5;
    const int nw = (gridDim.x * blockDim.x) >> 5;

    __half2 at2[4];
    {
        const float4 a0 = *(const float4*)&att[lane * 8 + 0];
        const float4 a1 = *(const float4*)&att[lane * 8 + 4];
        at2[0] = __floats2half2_rn(a0.x, a0.y);
        at2[1] = __floats2half2_rn(a0.z, a0.w);
        at2[2] = __floats2half2_rn(a1.x, a1.y);
        at2[3] = __floats2half2_rn(a1.z, a1.w);
    }
    const __half2 C02 = __float2half2_rn(0.2f);

    for (int n = w; n < NN; n += nw) {
        __half2 r2[4];
        {
            uint4 ur = *(const uint4*)&g_xr[n * HC + lane * 8];
            const __half2* rh = (const __half2*)&ur;
            r2[0] = rh[0]; r2[1] = rh[1]; r2[2] = rh[2]; r2[3] = rh[3];
        }

        __half2 acc2[4];
        acc2[0] = __float2half2_rn(0.f);
        acc2[1] = acc2[0]; acc2[2] = acc2[0]; acc2[3] = acc2[0];
        float D = 0.f;

        auto doedge1 = [&](uint4 ul) {
            const __half2* lh = (const __half2*)&ul;
            __half2 ps = __float2half2_rn(0.f);
#pragma unroll
            for (int i = 0; i < 4; i++) {
                __half2 z = __hadd2(lh[i], r2[i]);
                __half2 lk = __hmax2(z, __hmul2(z, C02));
                ps = __hfma2(lk, at2[i], ps);
            }
            float2 pf = __half22float2(ps);
            float p = pf.x + pf.y;
            p += __shfl_xor_sync(0xffffffffu, p, 4);
            p += __shfl_xor_sync(0xffffffffu, p, 2);
            p += __shfl_xor_sync(0xffffffffu, p, 1);
            const float a = __expf(p - 6.0f);
            D += a;
            const __half2 a2 = __float2half2_rn(a);
#pragma unroll
            for (int i = 0; i < 4; i++) acc2[i] = __hfma2(a2, lh[i], acc2[i]);
        };

        auto doedge2 = [&](uint4 ul0, uint4 ul1) {
            const __half2* lh0 = (const __half2*)&ul0;
            const __half2* lh1 = (const __half2*)&ul1;
            __half2 ps0 = __float2half2_rn(0.f);
            __half2 ps1 = ps0;
#pragma unroll
            for (int i = 0; i < 4; i++) {
                __half2 z0 = __hadd2(lh0[i], r2[i]);
                __half2 z1 = __hadd2(lh1[i], r2[i]);
                ps0 = __hfma2(__hmax2(z0, __hmul2(z0, C02)), at2[i], ps0);
                ps1 = __hfma2(__hmax2(z1, __hmul2(z1, C02)), at2[i], ps1);
            }
            __half2 ph = __hadd2(__lows2half2(ps0, ps1), __highs2half2(ps0, ps1));
#pragma unroll
            for (int s = 4; s > 0; s >>= 1) {
                unsigned pu = __shfl_xor_sync(0xffffffffu, *(unsigned*)&ph, s);
                ph = __hadd2(ph, *(__half2*)&pu);
            }
            float2 pf = __half22float2(ph);
            float a0 = __expf(pf.x - 6.0f);
            float a1 = __expf(pf.y - 6.0f);
            D += a0 + a1;
            const __half2 ah0 = __float2half2_rn(a0);
            const __half2 ah1 = __float2half2_rn(a1);
#pragma unroll
            for (int i = 0; i < 4; i++) {
                acc2[i] = __hfma2(ah0, lh0[i], acc2[i]);
                acc2[i] = __hfma2(ah1, lh1[i], acc2[i]);
            }
        };

        doedge1(*(const uint4*)&g_xl[n * HC + lane * 8]);   // self loop

        const int beg = g_off[n], end = g_off[n + 1];
        int e = beg;
        for (; e + 1 < end; e += 2) {
            const int s0 = g_csrc[e], s1 = g_csrc[e + 1];
            uint4 u0 = *(const uint4*)&g_xl[s0 * HC + lane * 8];
            uint4 u1 = *(const uint4*)&g_xl[s1 * HC + lane * 8];
            doedge2(u0, u1);
        }
        if (e < end) {
            const int s = g_csrc[e];
            doedge1(*(const uint4*)&g_xl[s * HC + lane * 8]);
        }

        const float inv = 1.f / (D + 1e-16f);
        float v[8];
#pragma unroll
        for (int i = 0; i < 4; i++) {
            float2 af = __half22float2(acc2[i]);
            float t0 = af.x * inv, t1 = af.y * inv;
            t0 += __shfl_xor_sync(0xffffffffu, t0, 8);
            t0 += __shfl_xor_sync(0xffffffffu, t0, 16);
            t1 += __shfl_xor_sync(0xffffffffu, t1, 8);
            t1 += __shfl_xor_sync(0xffffffffu, t1, 16);
            v[2 * i] = t0; v[2 * i + 1] = t1;
        }

        if (lane < 8) {
            const int g = batch[n];
            if (lane == 0) atomicAdd(&g_cnt[g], 1);
#pragma unroll
            for (int j = 0; j < 8; j++) {
                const int c = lane * 8 + j;
                float val = fmaf(0.25f, v[j], bgnn[c]);
                val = fmaxf(val, 0.01f * val);
                atomicAdd(&g_pool[g * CC + c], val);
            }
        }
    }
}

// ---------------- L4: final FC (4 graphs x 128 cols x 2 k-halves) ---------------
__global__ __launch_bounds__(256) void k_fc(const float* __restrict__ hy,
                                            const float* __restrict__ Wfc,
                                            const float* __restrict__ bfc,
                                            float* __restrict__ out) {
    const int gb = (blockIdx.x >> 1) * FC_GPB;
    const int ch = blockIdx.x & 1;
    const int j = threadIdx.x;
    const int cj = j & 127;
    const int col = ch * 128 + cj;
    const int kh = j >> 7;
    __shared__ float sh[FC_GPB][KD];
    __shared__ float red[FC_GPB][128];

#pragma unroll
    for (int gi = 0; gi < FC_GPB; gi++) {
        const int g = gb + gi;
        sh[gi][j] = hy[g * DENC_ + j];
        if (j < CC) {
            int c = g_cnt[g];
            float cn = c > 0 ? (float)c : 1.f;
            sh[gi][DENC_ + j] = g_pool[g * CC + j] / cn;
        }
    }
    __syncthreads();

    for (int t = blockIdx.x * 256 + j; t < NN; t += FC_BLOCKS * 256) g_deg[t] = 0;
    if (blockIdx.x == 0 && j == 0) g_done = 0u;

    float acc[FC_GPB];
#pragma unroll
    for (int gi = 0; gi < FC_GPB; gi++) acc[gi] = (kh == 0) ? bfc[col] : 0.f;

    const int k0 = kh * KHALF;
#pragma unroll 8
    for (int k = k0; k < k0 + KHALF; k++) {
        const float wv = Wfc[k * DENC_ + col];
#pragma unroll
        for (int gi = 0; gi < FC_GPB; gi++) acc[gi] = fmaf(sh[gi][k], wv, acc[gi]);
    }

    if (kh == 1) {
#pragma unroll
        for (int gi = 0; gi < FC_GPB; gi++) red[gi][cj] = acc[gi];
    }
    __syncthreads();
    if (kh == 0) {
#pragma unroll
        for (int gi = 0; gi < FC_GPB; gi++)
            out[(gb + gi) * DENC_ + col] = acc[gi] + red[gi][cj];
    }
}

// ---------------- launch ----------------
extern "C" void kernel_launch(void* const* d_in, const int* in_sizes, int n_in,
                              void* d_out, int out_size) {
    const float* hy   = (const float*)d_in[0];
    const float* x    = (const float*)d_in[1];
    const int*   ei   = (const int*)d_in[2];
    const int*   batch= (const int*)d_in[3];
    const float* Wl   = (const float*)d_in[4];
    const float* bl   = (const float*)d_in[5];
    const float* Wr   = (const float*)d_in[6];
    const float* br   = (const float*)d_in[7];
    const float* att  = (const float*)d_in[8];
    const float* bgnn = (const float*)d_in[9];
    const float* Wfc  = (const float*)d_in[10];
    const float* bfc  = (const float*)d_in[11];
    float* out = (float*)d_out;

    k_pre<<<PRE_BLOCKS, 1024>>>(Wl, Wr, ei);                   // #1
    k_mid<<<MTILES + SCAT_BLOCKS, 256>>>(x, bl, br, ei);       // #2 gemm first
    k_node<<<(NN + 7) / 8, 256>>>(att, bgnn, batch);           // #3
    k_fc<<<FC_BLOCKS, 256>>>(hy, Wfc, bfc, out);               // #4 (profiled)
}